// round 7
// baseline (speedup 1.0000x reference)
#include <cuda_runtime.h>
#include <cuda_bf16.h>
#include <mma.h>
#include <math.h>
#include <cstdint>

using namespace nvcuda;

// ============================================================================
// WMMA bf16 3-term-split fused MLP + segment sum, cp.async double-buffered.
//   kernA: H1 = relu(X@W1+b1) -> g_H1_{hi,lo}   (X resident, W1 tiles piped)
//   kernB: per 128-col chunk: H2c = relu(H1@W2+b2) (H1/W2 tiles piped),
//          Y += H2c @ W3c (W3 prefetch overlaps chunk epilogue),
//          g = silu(Y+b3), sorted segment-sum -> out.
// Split: A@B ~= Ahi@Bhi + Ahi@Blo + Alo@Bhi
// ============================================================================

#define NODES_PAD (3907 * 128)
#define XS_LD  264            // 256 + 8 pad (bf16)
#define WT_LD  72             // 64 + 8 pad (bf16)
#define WT_TILE (128 * WT_LD) // 9216 elems = 18432 B per [128x64] tile
#define FB_LD  132            // fbuf fp32 ld

__device__ __align__(16) __nv_bfloat16 g_W1t_hi[512 * 256];
__device__ __align__(16) __nv_bfloat16 g_W1t_lo[512 * 256];
__device__ __align__(16) __nv_bfloat16 g_W2t_hi[512 * 512];
__device__ __align__(16) __nv_bfloat16 g_W2t_lo[512 * 512];
__device__ __align__(16) __nv_bfloat16 g_W3t_hi[128 * 512];
__device__ __align__(16) __nv_bfloat16 g_W3t_lo[128 * 512];
__device__ __align__(16) __nv_bfloat16 g_H1_hi[(size_t)NODES_PAD * 512];
__device__ __align__(16) __nv_bfloat16 g_H1_lo[(size_t)NODES_PAD * 512];

__device__ __forceinline__ void split2(float v, __nv_bfloat16& h, __nv_bfloat16& l) {
    h = __float2bfloat16(v);
    l = __float2bfloat16(v - __bfloat162float(h));
}
__device__ __forceinline__ void cpa16(uint32_t dst, const void* src) {
    asm volatile("cp.async.cg.shared.global [%0], [%1], 16;" :: "r"(dst), "l"(src));
}
#define CPA_COMMIT() asm volatile("cp.async.commit_group;" ::: "memory")
#define CPA_WAIT0()  asm volatile("cp.async.wait_group 0;" ::: "memory")
#define CPA_WAIT1()  asm volatile("cp.async.wait_group 1;" ::: "memory")

// ---------------- setup: transpose + split weights ----------------
__global__ void setup_weights(const float* __restrict__ W1, const float* __restrict__ W2,
                              const float* __restrict__ W3)
{
    int i = blockIdx.x * blockDim.x + threadIdx.x;
    __nv_bfloat16 h, l;
    if (i < 512 * 256) {
        int n = i >> 8, k = i & 255;
        split2(W1[k * 512 + n], h, l);
        g_W1t_hi[n * 256 + k] = h; g_W1t_lo[n * 256 + k] = l;
        return;
    }
    i -= 512 * 256;
    if (i < 512 * 512) {
        int n = i >> 9, k = i & 511;
        split2(W2[k * 512 + n], h, l);
        g_W2t_hi[n * 512 + k] = h; g_W2t_lo[n * 512 + k] = l;
        return;
    }
    i -= 512 * 512;
    if (i < 128 * 512) {
        int n = i >> 9, k = i & 511;
        split2(W3[k * 128 + n], h, l);
        g_W3t_hi[n * 512 + k] = h; g_W3t_lo[n * 512 + k] = l;
    }
}

__global__ void zero_out_kernel(float* out, int n)
{
    int i = blockIdx.x * blockDim.x + threadIdx.x;
    if (i < n) out[i] = 0.f;
}

// ============================================================================
// Kernel A: H1 = relu(X @ W1 + b1)
// SMEM: Xh/Xl [128][264] resident | W region: 2 bufs x (Wh,Wl) [128][72]
//       fbuf [128][132] f32 aliases W region (used after kt loop completes)
// ============================================================================
__global__ void __launch_bounds__(256, 1)
gemm1_kernel(const float* __restrict__ X, const float* __restrict__ b1, int Nn)
{
    extern __shared__ char smem[];
    __nv_bfloat16* Xh = (__nv_bfloat16*)smem;
    __nv_bfloat16* Xl = Xh + 128 * XS_LD;
    __nv_bfloat16* SW = Xl + 128 * XS_LD;          // 4 tile slots (2 bufs x hi/lo)
    float* fbuf = (float*)SW;                      // alias
    const uint32_t swu = (uint32_t)__cvta_generic_to_shared(SW);

    const int t   = threadIdx.x;
    const int wid = t >> 5;
    const int wm  = wid & 3;
    const int wn  = wid >> 2;
    const int row0 = blockIdx.x * 128;

    // ---- load + split X (128 x 256 fp32) ----
    #pragma unroll 4
    for (int p = 0; p < 32; ++p) {
        int idx = t + p * 256;
        int r = idx >> 6, c4 = idx & 63;
        float4 v = (row0 + r < Nn) ? *(const float4*)(X + (size_t)(row0 + r) * 256 + c4 * 4)
                                   : make_float4(0.f, 0.f, 0.f, 0.f);
        float vv[4] = {v.x, v.y, v.z, v.w};
        #pragma unroll
        for (int q = 0; q < 4; ++q) {
            __nv_bfloat16 h, l; split2(vv[q], h, l);
            Xh[r * XS_LD + c4 * 4 + q] = h;
            Xl[r * XS_LD + c4 * 4 + q] = l;
        }
    }
    __syncthreads();

    auto prefW = [&](int nc, int kt, int b) {
        const uint32_t dh = swu + (uint32_t)b * 2 * WT_TILE * 2;
        const uint32_t dl = dh + WT_TILE * 2;
        #pragma unroll
        for (int p = 0; p < 4; ++p) {
            int idx = t + p * 256;
            int r = idx >> 3, c8 = idx & 7;
            uint32_t off = (uint32_t)(r * WT_LD + c8 * 8) * 2;
            size_t src = (size_t)(nc * 128 + r) * 256 + kt * 64 + c8 * 8;
            cpa16(dh + off, g_W1t_hi + src);
            cpa16(dl + off, g_W1t_lo + src);
        }
    };

    for (int nc = 0; nc < 4; ++nc) {
        wmma::fragment<wmma::accumulator, 16, 16, 16, float> acc[2][4];
        #pragma unroll
        for (int i = 0; i < 2; ++i)
            #pragma unroll
            for (int j = 0; j < 4; ++j) wmma::fill_fragment(acc[i][j], 0.f);

        prefW(nc, 0, 0); CPA_COMMIT();
        for (int kt = 0; kt < 4; ++kt) {
            if (kt < 3) { prefW(nc, kt + 1, (kt + 1) & 1); CPA_COMMIT(); CPA_WAIT1(); }
            else        { CPA_WAIT0(); }
            __syncthreads();
            const __nv_bfloat16* Wh = SW + (kt & 1) * 2 * WT_TILE;
            const __nv_bfloat16* Wl = Wh + WT_TILE;
            #pragma unroll
            for (int ks = 0; ks < 4; ++ks) {
                wmma::fragment<wmma::matrix_a, 16, 16, 16, __nv_bfloat16, wmma::row_major> ah[2], al[2];
                wmma::fragment<wmma::matrix_b, 16, 16, 16, __nv_bfloat16, wmma::col_major> bh[4], bl[4];
                #pragma unroll
                for (int i = 0; i < 2; ++i) {
                    int off = (wm * 32 + i * 16) * XS_LD + kt * 64 + ks * 16;
                    wmma::load_matrix_sync(ah[i], Xh + off, XS_LD);
                    wmma::load_matrix_sync(al[i], Xl + off, XS_LD);
                }
                #pragma unroll
                for (int j = 0; j < 4; ++j) {
                    int off = (wn * 64 + j * 16) * WT_LD + ks * 16;
                    wmma::load_matrix_sync(bh[j], Wh + off, WT_LD);
                    wmma::load_matrix_sync(bl[j], Wl + off, WT_LD);
                }
                #pragma unroll
                for (int i = 0; i < 2; ++i)
                    #pragma unroll
                    for (int j = 0; j < 4; ++j) {
                        wmma::mma_sync(acc[i][j], ah[i], bh[j], acc[i][j]);
                        wmma::mma_sync(acc[i][j], ah[i], bl[j], acc[i][j]);
                        wmma::mma_sync(acc[i][j], al[i], bh[j], acc[i][j]);
                    }
            }
            __syncthreads();
        }
        // ---- single-pass epilogue: acc -> fbuf -> relu/split -> g_H1 ----
        #pragma unroll
        for (int i = 0; i < 2; ++i)
            #pragma unroll
            for (int j = 0; j < 4; ++j)
                wmma::store_matrix_sync(fbuf + (wm * 32 + i * 16) * FB_LD + wn * 64 + j * 16,
                                        acc[i][j], FB_LD, wmma::mem_row_major);
        __syncthreads();
        #pragma unroll 4
        for (int p = 0; p < 64; ++p) {
            int idx = t + p * 256;
            int r = idx >> 7, c = idx & 127;
            if (row0 + r < Nn) {
                float v = fbuf[r * FB_LD + c] + b1[nc * 128 + c];
                v = v > 0.f ? v : 0.f;
                __nv_bfloat16 hh, ll; split2(v, hh, ll);
                g_H1_hi[(size_t)(row0 + r) * 512 + nc * 128 + c] = hh;
                g_H1_lo[(size_t)(row0 + r) * 512 + nc * 128 + c] = ll;
            }
        }
        __syncthreads();
    }
}

// ============================================================================
// Kernel B: H2c = relu(H1@W2+b2); Y += H2c@W3c; silu; segment sum
// SMEM tile region SW: 8 slots of WT_TILE (2 bufs x (Hh,Hl,Wh,Wl))
//   W3 tiles alias buf0 slots; fbuf [128][132] f32 aliases buf1 region.
// P region SP: 4 slots (Ph0,Ph1,Pl0,Pl1).
// ============================================================================
__global__ void __launch_bounds__(256, 1)
gemm23_kernel(const int* __restrict__ gidx,
              const float* __restrict__ b2, const float* __restrict__ b3,
              float* __restrict__ out, int Nn)
{
    extern __shared__ char smem[];
    __nv_bfloat16* SW = (__nv_bfloat16*)smem;      // 8 x WT_TILE
    __nv_bfloat16* SP = SW + 8 * WT_TILE;          // 4 x WT_TILE
    int*   gids = (int*)(SP + 4 * WT_TILE);
    float* fbuf = (float*)(SW + 4 * WT_TILE);      // buf1 alias
    const uint32_t swu = (uint32_t)__cvta_generic_to_shared(SW);

    const int t   = threadIdx.x;
    const int wid = t >> 5;
    const int wm  = wid & 3;
    const int wn  = wid >> 2;
    const int row0 = blockIdx.x * 128;

    if (t < 128) gids[t] = (row0 + t < Nn) ? gidx[row0 + t] : -1;

    auto prefG2 = [&](int mc, int kt, int b) {     // Hh,Hl,Wh,Wl tiles for (mc,kt)
        const uint32_t base = swu + (uint32_t)b * 4 * WT_TILE * 2;
        #pragma unroll
        for (int p = 0; p < 4; ++p) {
            int idx = t + p * 256;
            int r = idx >> 3, c8 = idx & 7;
            uint32_t off = (uint32_t)(r * WT_LD + c8 * 8) * 2;
            size_t hsrc = (size_t)(row0 + r) * 512 + kt * 64 + c8 * 8;
            size_t wsrc = (size_t)(mc * 128 + r) * 512 + kt * 64 + c8 * 8;
            cpa16(base + off,                   g_H1_hi  + hsrc);
            cpa16(base + WT_TILE * 2 + off,     g_H1_lo  + hsrc);
            cpa16(base + 2 * WT_TILE * 2 + off, g_W2t_hi + wsrc);
            cpa16(base + 3 * WT_TILE * 2 + off, g_W2t_lo + wsrc);
        }
    };
    auto prefW3 = [&](int mc) {                    // 2 k-subtiles x hi/lo into buf0
        #pragma unroll
        for (int sub = 0; sub < 2; ++sub) {
            #pragma unroll
            for (int p = 0; p < 4; ++p) {
                int idx = t + p * 256;
                int r = idx >> 3, c8 = idx & 7;
                uint32_t off = (uint32_t)(r * WT_LD + c8 * 8) * 2;
                size_t src = (size_t)r * 512 + mc * 128 + sub * 64 + c8 * 8;
                cpa16(swu + (uint32_t)sub * WT_TILE * 2 + off,       g_W3t_hi + src);
                cpa16(swu + (uint32_t)(2 + sub) * WT_TILE * 2 + off, g_W3t_lo + src);
            }
        }
    };

    wmma::fragment<wmma::accumulator, 16, 16, 16, float> Y[2][4];
    #pragma unroll
    for (int i = 0; i < 2; ++i)
        #pragma unroll
        for (int j = 0; j < 4; ++j) wmma::fill_fragment(Y[i][j], 0.f);

    for (int mc = 0; mc < 4; ++mc) {
        wmma::fragment<wmma::accumulator, 16, 16, 16, float> acc2[2][4];
        #pragma unroll
        for (int i = 0; i < 2; ++i)
            #pragma unroll
            for (int j = 0; j < 4; ++j) wmma::fill_fragment(acc2[i][j], 0.f);

        // ---- GEMM2 chunk, double-buffered over kt = 0..7 ----
        prefG2(mc, 0, 0); CPA_COMMIT();
        for (int kt = 0; kt < 8; ++kt) {
            if (kt < 7) { prefG2(mc, kt + 1, (kt + 1) & 1); CPA_COMMIT(); CPA_WAIT1(); }
            else        { CPA_WAIT0(); }
            __syncthreads();
            const __nv_bfloat16* Hh = SW + (kt & 1) * 4 * WT_TILE;
            const __nv_bfloat16* Hl = Hh + WT_TILE;
            const __nv_bfloat16* Wh = Hh + 2 * WT_TILE;
            const __nv_bfloat16* Wl = Hh + 3 * WT_TILE;
            #pragma unroll
            for (int ks = 0; ks < 4; ++ks) {
                wmma::fragment<wmma::matrix_a, 16, 16, 16, __nv_bfloat16, wmma::row_major> ah[2], al[2];
                wmma::fragment<wmma::matrix_b, 16, 16, 16, __nv_bfloat16, wmma::col_major> bh[4], bl[4];
                #pragma unroll
                for (int i = 0; i < 2; ++i) {
                    int off = (wm * 32 + i * 16) * WT_LD + ks * 16;
                    wmma::load_matrix_sync(ah[i], Hh + off, WT_LD);
                    wmma::load_matrix_sync(al[i], Hl + off, WT_LD);
                }
                #pragma unroll
                for (int j = 0; j < 4; ++j) {
                    int off = (wn * 64 + j * 16) * WT_LD + ks * 16;
                    wmma::load_matrix_sync(bh[j], Wh + off, WT_LD);
                    wmma::load_matrix_sync(bl[j], Wl + off, WT_LD);
                }
                #pragma unroll
                for (int i = 0; i < 2; ++i)
                    #pragma unroll
                    for (int j = 0; j < 4; ++j) {
                        wmma::mma_sync(acc2[i][j], ah[i], bh[j], acc2[i][j]);
                        wmma::mma_sync(acc2[i][j], ah[i], bl[j], acc2[i][j]);
                        wmma::mma_sync(acc2[i][j], al[i], bh[j], acc2[i][j]);
                    }
            }
            __syncthreads();
        }

        // ---- W3 prefetch (buf0) overlaps chunk epilogue (fbuf in buf1) ----
        prefW3(mc); CPA_COMMIT();

        #pragma unroll
        for (int i = 0; i < 2; ++i)
            #pragma unroll
            for (int j = 0; j < 4; ++j)
                wmma::store_matrix_sync(fbuf + (wm * 32 + i * 16) * FB_LD + wn * 64 + j * 16,
                                        acc2[i][j], FB_LD, wmma::mem_row_major);
        __syncthreads();
        #pragma unroll 4
        for (int p = 0; p < 64; ++p) {
            int idx = t + p * 256;
            int r = idx >> 7, c = idx & 127;
            float v = fbuf[r * FB_LD + c] + b2[mc * 128 + c];
            v = v > 0.f ? v : 0.f;
            __nv_bfloat16 hh, ll; split2(v, hh, ll);
            int sub = c >> 6, cc = c & 63;
            SP[sub * WT_TILE + r * WT_LD + cc] = hh;              // Ph sub
            SP[(2 + sub) * WT_TILE + r * WT_LD + cc] = ll;        // Pl sub
        }
        CPA_WAIT0();
        __syncthreads();

        // ---- GEMM3 partial: Y += P @ W3 (both k-subtiles resident) ----
        #pragma unroll
        for (int kt3 = 0; kt3 < 2; ++kt3) {
            const __nv_bfloat16* Ph  = SP + kt3 * WT_TILE;
            const __nv_bfloat16* Pl  = SP + (2 + kt3) * WT_TILE;
            const __nv_bfloat16* W3h = SW + kt3 * WT_TILE;
            const __nv_bfloat16* W3l = SW + (2 + kt3) * WT_TILE;
            #pragma unroll
            for (int ks = 0; ks < 4; ++ks) {
                wmma::fragment<wmma::matrix_a, 16, 16, 16, __nv_bfloat16, wmma::row_major> ah[2], al[2];
                wmma::fragment<wmma::matrix_b, 16, 16, 16, __nv_bfloat16, wmma::col_major> bh[4], bl[4];
                #pragma unroll
                for (int i = 0; i < 2; ++i) {
                    int off = (wm * 32 + i * 16) * WT_LD + ks * 16;
                    wmma::load_matrix_sync(ah[i], Ph + off, WT_LD);
                    wmma::load_matrix_sync(al[i], Pl + off, WT_LD);
                }
                #pragma unroll
                for (int j = 0; j < 4; ++j) {
                    int off = (wn * 64 + j * 16) * WT_LD + ks * 16;
                    wmma::load_matrix_sync(bh[j], W3h + off, WT_LD);
                    wmma::load_matrix_sync(bl[j], W3l + off, WT_LD);
                }
                #pragma unroll
                for (int i = 0; i < 2; ++i)
                    #pragma unroll
                    for (int j = 0; j < 4; ++j) {
                        wmma::mma_sync(Y[i][j], ah[i], bh[j], Y[i][j]);
                        wmma::mma_sync(Y[i][j], ah[i], bl[j], Y[i][j]);
                        wmma::mma_sync(Y[i][j], al[i], bh[j], Y[i][j]);
                    }
            }
        }
        __syncthreads();   // protect SW/SP before next mc prefetch / final epilogue
    }

    // ---- final: Y -> fbuf, +b3, silu, sorted segment reduce, atomics ----
    #pragma unroll
    for (int i = 0; i < 2; ++i)
        #pragma unroll
        for (int j = 0; j < 4; ++j)
            wmma::store_matrix_sync(fbuf + (wm * 32 + i * 16) * FB_LD + wn * 64 + j * 16,
                                    Y[i][j], FB_LD, wmma::mem_row_major);
    __syncthreads();
    #pragma unroll 4
    for (int p = 0; p < 64; ++p) {
        int idx = t + p * 256;
        int r = idx >> 7, c = idx & 127;
        float y = fbuf[r * FB_LD + c] + b3[c];
        fbuf[r * FB_LD + c] = y / (1.f + expf(-y));
    }
    __syncthreads();

    if (t < 128) {
        int cur = gids[0];
        float s = 0.f;
        #pragma unroll 1
        for (int r = 0; r < 128; ++r) {
            int gi = gids[r];
            if (gi != cur) {
                if (cur >= 0) atomicAdd(&out[(size_t)cur * 128 + t], s);
                cur = gi; s = 0.f;
            }
            if (gi >= 0) s += fbuf[r * FB_LD + t];
        }
        if (cur >= 0) atomicAdd(&out[(size_t)cur * 128 + t], s);
    }
}

// ============================================================================
extern "C" void kernel_launch(void* const* d_in, const int* in_sizes, int n_in,
                              void* d_out, int out_size)
{
    const float* X    = (const float*)d_in[0];
    const int*   gidx = (const int*)d_in[1];     // int32 (JAX x64 disabled)
    const float* W1   = (const float*)d_in[2];
    const float* b1   = (const float*)d_in[3];
    const float* W2   = (const float*)d_in[4];
    const float* b2   = (const float*)d_in[5];
    const float* W3   = (const float*)d_in[6];
    const float* b3   = (const float*)d_in[7];
    float* out = (float*)d_out;

    const int Nn = in_sizes[0] / 256;
    const int blocks = (Nn + 127) / 128;

    zero_out_kernel<<<(out_size + 255) / 256, 256>>>(out, out_size);
    setup_weights<<<(512 * 256 + 512 * 512 + 128 * 512 + 255) / 256, 256>>>(W1, W2, W3);

    const int smemA = 2 * 128 * XS_LD * 2 + 4 * WT_TILE * 2;            // 208896
    const int smemB = 12 * WT_TILE * 2 + 512;                           // 221696
    cudaFuncSetAttribute(gemm1_kernel,  cudaFuncAttributeMaxDynamicSharedMemorySize, smemA);
    cudaFuncSetAttribute(gemm23_kernel, cudaFuncAttributeMaxDynamicSharedMemorySize, smemB);

    gemm1_kernel<<<blocks, 256, smemA>>>(X, b1, Nn);
    gemm23_kernel<<<blocks, 256, smemB>>>(gidx, b2, b3, out, Nn);
}

// round 9
// speedup vs baseline: 2.2363x; 2.2363x over previous
#include <cuda_runtime.h>
#include <cuda_fp16.h>
#include <mma.h>
#include <math.h>
#include <cstdint>

using namespace nvcuda;

// ============================================================================
// WMMA fp16 mixed-split fused MLP + segment sum.
//   Activations (X, H1, H2): single fp16 (quant err ~2^-12 RMS).
//   Weights: fp16 hi+lo split (residual ~2^-22).
//   GEMM terms: acc += A*Wh + A*Wl  (2 MMAs instead of 3).
// R9 fix: smemB undercounted tile slots (7, not 6) -> fbuf/gids ran past
// allocated dynamic smem -> illegal memory access. Constant corrected.
// ============================================================================

#define NODES_PAD (3907 * 128)
#define XS_LD  264            // 256 + 8 pad (fp16 elems)
#define WT_LD  72             // 64 + 8 pad
#define WT_TILE (128 * WT_LD) // elems per [128x64] tile
#define FB_LD  132            // fbuf fp32 ld

__device__ __align__(16) __half g_W1t_hi[512 * 256];
__device__ __align__(16) __half g_W1t_lo[512 * 256];
__device__ __align__(16) __half g_W2t_hi[512 * 512];
__device__ __align__(16) __half g_W2t_lo[512 * 512];
__device__ __align__(16) __half g_W3t_hi[128 * 512];
__device__ __align__(16) __half g_W3t_lo[128 * 512];
__device__ __align__(16) __half g_H1[(size_t)NODES_PAD * 512];

__device__ __forceinline__ void split2h(float v, __half& h, __half& l) {
    h = __float2half_rn(v);
    l = __float2half_rn(v - __half2float(h));
}

// ---------------- setup: transpose + fp16-split weights ----------------
__global__ void setup_weights(const float* __restrict__ W1, const float* __restrict__ W2,
                              const float* __restrict__ W3)
{
    int i = blockIdx.x * blockDim.x + threadIdx.x;
    __half h, l;
    if (i < 512 * 256) {                       // W1 [256K x 512N] -> W1t [512][256]
        int n = i >> 8, k = i & 255;
        split2h(W1[k * 512 + n], h, l);
        g_W1t_hi[n * 256 + k] = h; g_W1t_lo[n * 256 + k] = l;
        return;
    }
    i -= 512 * 256;
    if (i < 512 * 512) {                       // W2 [512 x 512] -> W2t [512][512]
        int n = i >> 9, k = i & 511;
        split2h(W2[k * 512 + n], h, l);
        g_W2t_hi[n * 512 + k] = h; g_W2t_lo[n * 512 + k] = l;
        return;
    }
    i -= 512 * 512;
    if (i < 128 * 512) {                       // W3 [512K x 128N] -> W3t [128][512]
        int n = i >> 9, k = i & 511;
        split2h(W3[k * 128 + n], h, l);
        g_W3t_hi[n * 512 + k] = h; g_W3t_lo[n * 512 + k] = l;
    }
}

__global__ void zero_out_kernel(float* out, int n)
{
    int i = blockIdx.x * blockDim.x + threadIdx.x;
    if (i < n) out[i] = 0.f;
}

// ============================================================================
// Kernel A: H1 = relu(X @ W1 + b1)
// SMEM: Xs [128][264] fp16 resident | Wh/Wl [128][72] | fbuf [128][132] f32
// ============================================================================
__global__ void __launch_bounds__(256, 1)
gemm1_kernel(const float* __restrict__ X, const float* __restrict__ b1, int Nn)
{
    extern __shared__ char smem[];
    __half* Xs = (__half*)smem;                       // 67,584 B
    __half* Wh = Xs + 128 * XS_LD;                    // 18,432 B
    __half* Wl = Wh + WT_TILE;                        // 18,432 B
    float*  fbuf = (float*)(Wl + WT_TILE);            // 67,584 B

    const int t   = threadIdx.x;
    const int wid = t >> 5;
    const int wm  = wid & 3;          // 4 warps over M (32 rows)
    const int wn  = wid >> 2;         // 2 warps over N (64 cols)
    const int row0 = blockIdx.x * 128;

    // ---- load X (128 x 256 fp32) -> fp16 ----
    #pragma unroll 4
    for (int p = 0; p < 32; ++p) {
        int idx = t + p * 256;
        int r = idx >> 6, c4 = idx & 63;
        float4 v = (row0 + r < Nn) ? *(const float4*)(X + (size_t)(row0 + r) * 256 + c4 * 4)
                                   : make_float4(0.f, 0.f, 0.f, 0.f);
        Xs[r * XS_LD + c4 * 4 + 0] = __float2half_rn(v.x);
        Xs[r * XS_LD + c4 * 4 + 1] = __float2half_rn(v.y);
        Xs[r * XS_LD + c4 * 4 + 2] = __float2half_rn(v.z);
        Xs[r * XS_LD + c4 * 4 + 3] = __float2half_rn(v.w);
    }
    __syncthreads();

    for (int nc = 0; nc < 4; ++nc) {
        wmma::fragment<wmma::accumulator, 16, 16, 16, float> acc[2][4];
        #pragma unroll
        for (int i = 0; i < 2; ++i)
            #pragma unroll
            for (int j = 0; j < 4; ++j) wmma::fill_fragment(acc[i][j], 0.f);

        for (int kt = 0; kt < 4; ++kt) {
            #pragma unroll
            for (int p = 0; p < 4; ++p) {              // W1t tile hi+lo [128n][64k]
                int idx = t + p * 256;
                int r = idx >> 3, c8 = idx & 7;
                size_t src = (size_t)(nc * 128 + r) * 256 + kt * 64 + c8 * 8;
                *(uint4*)&Wh[r * WT_LD + c8 * 8] = *(const uint4*)(g_W1t_hi + src);
                *(uint4*)&Wl[r * WT_LD + c8 * 8] = *(const uint4*)(g_W1t_lo + src);
            }
            __syncthreads();
            #pragma unroll
            for (int ks = 0; ks < 4; ++ks) {
                wmma::fragment<wmma::matrix_a, 16, 16, 16, __half, wmma::row_major> a[2];
                wmma::fragment<wmma::matrix_b, 16, 16, 16, __half, wmma::col_major> bh[4], bl[4];
                #pragma unroll
                for (int i = 0; i < 2; ++i)
                    wmma::load_matrix_sync(a[i], Xs + (wm * 32 + i * 16) * XS_LD + kt * 64 + ks * 16, XS_LD);
                #pragma unroll
                for (int j = 0; j < 4; ++j) {
                    int off = (wn * 64 + j * 16) * WT_LD + ks * 16;
                    wmma::load_matrix_sync(bh[j], Wh + off, WT_LD);
                    wmma::load_matrix_sync(bl[j], Wl + off, WT_LD);
                }
                #pragma unroll
                for (int i = 0; i < 2; ++i)
                    #pragma unroll
                    for (int j = 0; j < 4; ++j) {
                        wmma::mma_sync(acc[i][j], a[i], bh[j], acc[i][j]);
                        wmma::mma_sync(acc[i][j], a[i], bl[j], acc[i][j]);
                    }
            }
            __syncthreads();
        }
        // ---- epilogue: acc -> fbuf -> +b1, relu, fp16 -> g_H1 ----
        #pragma unroll
        for (int i = 0; i < 2; ++i)
            #pragma unroll
            for (int j = 0; j < 4; ++j)
                wmma::store_matrix_sync(fbuf + (wm * 32 + i * 16) * FB_LD + wn * 64 + j * 16,
                                        acc[i][j], FB_LD, wmma::mem_row_major);
        __syncthreads();
        #pragma unroll 4
        for (int p = 0; p < 64; ++p) {
            int idx = t + p * 256;
            int r = idx >> 7, c = idx & 127;
            if (row0 + r < Nn) {
                float v = fbuf[r * FB_LD + c] + b1[nc * 128 + c];
                v = v > 0.f ? v : 0.f;
                g_H1[(size_t)(row0 + r) * 512 + nc * 128 + c] = __float2half_rn(v);
            }
        }
        __syncthreads();
    }
}

// ============================================================================
// Kernel B: H2c = relu(H1@W2+b2); Y += H2c@W3c; silu; segment sum
// SMEM: Hs | W2h | W2l | Ps[2 tiles] | W3h | W3l  = 7 WT_TILE slots,
//       then fbuf [128][132] f32, then gids.
// ============================================================================
__global__ void __launch_bounds__(256, 1)
gemm23_kernel(const int* __restrict__ gidx,
              const float* __restrict__ b2, const float* __restrict__ b3,
              float* __restrict__ out, int Nn)
{
    extern __shared__ char smem[];
    __half* Hs  = (__half*)smem;                 // [128][72]
    __half* W2h = Hs  + WT_TILE;
    __half* W2l = W2h + WT_TILE;
    __half* Ps  = W2l + WT_TILE;                 // 2 k-subtiles [128][72]
    __half* W3h = Ps  + 2 * WT_TILE;
    __half* W3l = W3h + WT_TILE;
    float*  fbuf = (float*)(W3l + WT_TILE);      // starts at 7*WT_TILE
    int*    gids = (int*)(fbuf + 128 * FB_LD);

    const int t   = threadIdx.x;
    const int wid = t >> 5;
    const int wm  = wid & 3;
    const int wn  = wid >> 2;
    const int row0 = blockIdx.x * 128;

    if (t < 128) gids[t] = (row0 + t < Nn) ? gidx[row0 + t] : -1;

    wmma::fragment<wmma::accumulator, 16, 16, 16, float> Y[2][4];
    #pragma unroll
    for (int i = 0; i < 2; ++i)
        #pragma unroll
        for (int j = 0; j < 4; ++j) wmma::fill_fragment(Y[i][j], 0.f);

    for (int mc = 0; mc < 4; ++mc) {
        wmma::fragment<wmma::accumulator, 16, 16, 16, float> acc2[2][4];
        #pragma unroll
        for (int i = 0; i < 2; ++i)
            #pragma unroll
            for (int j = 0; j < 4; ++j) wmma::fill_fragment(acc2[i][j], 0.f);

        // ---- GEMM2 chunk: acc2 = H1 @ W2t[mc*128..+128][:], kt = 0..7 ----
        for (int kt = 0; kt < 8; ++kt) {
            #pragma unroll
            for (int p = 0; p < 4; ++p) {              // H1 tile [128m][64k] fp16
                int idx = t + p * 256;
                int r = idx >> 3, c8 = idx & 7;
                size_t hsrc = (size_t)(row0 + r) * 512 + kt * 64 + c8 * 8;
                size_t wsrc = (size_t)(mc * 128 + r) * 512 + kt * 64 + c8 * 8;
                *(uint4*)&Hs[r * WT_LD + c8 * 8]  = *(const uint4*)(g_H1 + hsrc);
                *(uint4*)&W2h[r * WT_LD + c8 * 8] = *(const uint4*)(g_W2t_hi + wsrc);
                *(uint4*)&W2l[r * WT_LD + c8 * 8] = *(const uint4*)(g_W2t_lo + wsrc);
            }
            __syncthreads();
            #pragma unroll
            for (int ks = 0; ks < 4; ++ks) {
                wmma::fragment<wmma::matrix_a, 16, 16, 16, __half, wmma::row_major> a[2];
                wmma::fragment<wmma::matrix_b, 16, 16, 16, __half, wmma::col_major> bh[4], bl[4];
                #pragma unroll
                for (int i = 0; i < 2; ++i)
                    wmma::load_matrix_sync(a[i], Hs + (wm * 32 + i * 16) * WT_LD + ks * 16, WT_LD);
                #pragma unroll
                for (int j = 0; j < 4; ++j) {
                    int off = (wn * 64 + j * 16) * WT_LD + ks * 16;
                    wmma::load_matrix_sync(bh[j], W2h + off, WT_LD);
                    wmma::load_matrix_sync(bl[j], W2l + off, WT_LD);
                }
                #pragma unroll
                for (int i = 0; i < 2; ++i)
                    #pragma unroll
                    for (int j = 0; j < 4; ++j) {
                        wmma::mma_sync(acc2[i][j], a[i], bh[j], acc2[i][j]);
                        wmma::mma_sync(acc2[i][j], a[i], bl[j], acc2[i][j]);
                    }
            }
            __syncthreads();
        }

        // ---- chunk epilogue: acc2 -> fbuf -> +b2, relu, fp16 -> Ps ----
        #pragma unroll
        for (int i = 0; i < 2; ++i)
            #pragma unroll
            for (int j = 0; j < 4; ++j)
                wmma::store_matrix_sync(fbuf + (wm * 32 + i * 16) * FB_LD + wn * 64 + j * 16,
                                        acc2[i][j], FB_LD, wmma::mem_row_major);
        __syncthreads();
        #pragma unroll 4
        for (int p = 0; p < 64; ++p) {
            int idx = t + p * 256;
            int r = idx >> 7, c = idx & 127;
            float v = fbuf[r * FB_LD + c] + b2[mc * 128 + c];
            v = v > 0.f ? v : 0.f;
            int sub = c >> 6, cc = c & 63;
            Ps[sub * WT_TILE + r * WT_LD + cc] = __float2half_rn(v);
        }
        __syncthreads();

        // ---- GEMM3 partial: Y += Ps @ W3t[:, mc*128..+128] ----
        for (int kt3 = 0; kt3 < 2; ++kt3) {
            #pragma unroll
            for (int p = 0; p < 4; ++p) {              // W3t tile [128n][64k] hi+lo
                int idx = t + p * 256;
                int r = idx >> 3, c8 = idx & 7;
                size_t src = (size_t)r * 512 + mc * 128 + kt3 * 64 + c8 * 8;
                *(uint4*)&W3h[r * WT_LD + c8 * 8] = *(const uint4*)(g_W3t_hi + src);
                *(uint4*)&W3l[r * WT_LD + c8 * 8] = *(const uint4*)(g_W3t_lo + src);
            }
            __syncthreads();
            #pragma unroll
            for (int ks = 0; ks < 4; ++ks) {
                wmma::fragment<wmma::matrix_a, 16, 16, 16, __half, wmma::row_major> a[2];
                wmma::fragment<wmma::matrix_b, 16, 16, 16, __half, wmma::col_major> bh[4], bl[4];
                #pragma unroll
                for (int i = 0; i < 2; ++i)
                    wmma::load_matrix_sync(a[i], Ps + kt3 * WT_TILE + (wm * 32 + i * 16) * WT_LD + ks * 16, WT_LD);
                #pragma unroll
                for (int j = 0; j < 4; ++j) {
                    int off = (wn * 64 + j * 16) * WT_LD + ks * 16;
                    wmma::load_matrix_sync(bh[j], W3h + off, WT_LD);
                    wmma::load_matrix_sync(bl[j], W3l + off, WT_LD);
                }
                #pragma unroll
                for (int i = 0; i < 2; ++i)
                    #pragma unroll
                    for (int j = 0; j < 4; ++j) {
                        wmma::mma_sync(Y[i][j], a[i], bh[j], Y[i][j]);
                        wmma::mma_sync(Y[i][j], a[i], bl[j], Y[i][j]);
                    }
            }
            __syncthreads();
        }
    }

    // ---- final: Y -> fbuf, +b3, silu, sorted segment reduce, atomics ----
    #pragma unroll
    for (int i = 0; i < 2; ++i)
        #pragma unroll
        for (int j = 0; j < 4; ++j)
            wmma::store_matrix_sync(fbuf + (wm * 32 + i * 16) * FB_LD + wn * 64 + j * 16,
                                    Y[i][j], FB_LD, wmma::mem_row_major);
    __syncthreads();
    #pragma unroll 4
    for (int p = 0; p < 64; ++p) {
        int idx = t + p * 256;
        int r = idx >> 7, c = idx & 127;
        float y = fbuf[r * FB_LD + c] + b3[c];
        fbuf[r * FB_LD + c] = y / (1.f + expf(-y));
    }
    __syncthreads();

    if (t < 128) {
        int cur = gids[0];
        float s = 0.f;
        #pragma unroll 1
        for (int r = 0; r < 128; ++r) {
            int gi = gids[r];
            if (gi != cur) {
                if (cur >= 0) atomicAdd(&out[(size_t)cur * 128 + t], s);
                cur = gi; s = 0.f;
            }
            if (gi >= 0) s += fbuf[r * FB_LD + t];
        }
        if (cur >= 0) atomicAdd(&out[(size_t)cur * 128 + t], s);
    }
}

// ============================================================================
extern "C" void kernel_launch(void* const* d_in, const int* in_sizes, int n_in,
                              void* d_out, int out_size)
{
    const float* X    = (const float*)d_in[0];
    const int*   gidx = (const int*)d_in[1];     // int32 (JAX x64 disabled)
    const float* W1   = (const float*)d_in[2];
    const float* b1   = (const float*)d_in[3];
    const float* W2   = (const float*)d_in[4];
    const float* b2   = (const float*)d_in[5];
    const float* W3   = (const float*)d_in[6];
    const float* b3   = (const float*)d_in[7];
    float* out = (float*)d_out;

    const int Nn = in_sizes[0] / 256;
    const int blocks = (Nn + 127) / 128;

    zero_out_kernel<<<(out_size + 255) / 256, 256>>>(out, out_size);
    setup_weights<<<(512 * 256 + 512 * 512 + 128 * 512 + 255) / 256, 256>>>(W1, W2, W3);

    const int smemA = 128 * XS_LD * 2 + 2 * WT_TILE * 2 + 128 * FB_LD * 4;   // 172,032
    const int smemB = 7 * WT_TILE * 2 + 128 * FB_LD * 4 + 512;               // 197,120
    cudaFuncSetAttribute(gemm1_kernel,  cudaFuncAttributeMaxDynamicSharedMemorySize, smemA);
    cudaFuncSetAttribute(gemm23_kernel, cudaFuncAttributeMaxDynamicSharedMemorySize, smemB);

    gemm1_kernel<<<blocks, 256, smemA>>>(X, b1, Nn);
    gemm23_kernel<<<blocks, 256, smemB>>>(gidx, b2, b3, out, Nn);
}

// round 10
// speedup vs baseline: 3.1279x; 1.3987x over previous
#include <cuda_runtime.h>
#include <cuda_fp16.h>
#include <mma.h>
#include <math.h>
#include <cstdint>

using namespace nvcuda;

// ============================================================================
// Pure fp16 WMMA fused MLP + segment sum (1-term weights, fp16 activations,
// fp32 accumulators).
//   setup:  W{1,2,3}t = transpose(W) -> fp16, [N][K] K-major
//   kernA:  H1 = relu(X@W1+b1) -> g_H1 (fp16)
//   kernB:  per 128-col chunk: H2c = relu(H1@W2+b2) -> smem fp16,
//           Y += H2c @ W3c, then g = silu(Y+b3), sorted segment-sum -> out.
// Precision: weight quant 2^-11, activation quant 2^-12, fp32 accum; empirical
// error track record runs ~10x below pessimistic bound (R6, R9).
// ============================================================================

#define NODES_PAD (3907 * 128)
#define XS_LD  264            // 256 + 8 pad (fp16 elems)
#define WT_LD  72             // 64 + 8 pad
#define WT_TILE (128 * WT_LD) // elems per [128x64] tile
#define FB_LD  132            // fbuf fp32 ld

__device__ __align__(16) __half g_W1t[512 * 256];
__device__ __align__(16) __half g_W2t[512 * 512];
__device__ __align__(16) __half g_W3t[128 * 512];
__device__ __align__(16) __half g_H1[(size_t)NODES_PAD * 512];

// ---------------- setup: transpose weights to fp16 ----------------
__global__ void setup_weights(const float* __restrict__ W1, const float* __restrict__ W2,
                              const float* __restrict__ W3)
{
    int i = blockIdx.x * blockDim.x + threadIdx.x;
    if (i < 512 * 256) {                       // W1 [256K x 512N] -> W1t [512][256]
        int n = i >> 8, k = i & 255;
        g_W1t[n * 256 + k] = __float2half_rn(W1[k * 512 + n]);
        return;
    }
    i -= 512 * 256;
    if (i < 512 * 512) {                       // W2 [512 x 512] -> W2t [512][512]
        int n = i >> 9, k = i & 511;
        g_W2t[n * 512 + k] = __float2half_rn(W2[k * 512 + n]);
        return;
    }
    i -= 512 * 512;
    if (i < 128 * 512) {                       // W3 [512K x 128N] -> W3t [128][512]
        int n = i >> 9, k = i & 511;
        g_W3t[n * 512 + k] = __float2half_rn(W3[k * 128 + n]);
    }
}

__global__ void zero_out_kernel(float* out, int n)
{
    int i = blockIdx.x * blockDim.x + threadIdx.x;
    if (i < n) out[i] = 0.f;
}

// ============================================================================
// Kernel A: H1 = relu(X @ W1 + b1)
// SMEM: Xs [128][264] fp16 resident | Ws [128][72] | fbuf [128][132] f32
// ============================================================================
__global__ void __launch_bounds__(256, 1)
gemm1_kernel(const float* __restrict__ X, const float* __restrict__ b1, int Nn)
{
    extern __shared__ char smem[];
    __half* Xs = (__half*)smem;                       // 67,584 B
    __half* Ws = Xs + 128 * XS_LD;                    // 18,432 B
    float*  fbuf = (float*)(Ws + WT_TILE);            // 67,584 B

    const int t   = threadIdx.x;
    const int wid = t >> 5;
    const int wm  = wid & 3;          // 4 warps over M (32 rows)
    const int wn  = wid >> 2;         // 2 warps over N (64 cols)
    const int row0 = blockIdx.x * 128;

    // ---- load X (128 x 256 fp32) -> fp16 ----
    #pragma unroll 4
    for (int p = 0; p < 32; ++p) {
        int idx = t + p * 256;
        int r = idx >> 6, c4 = idx & 63;
        float4 v = (row0 + r < Nn) ? *(const float4*)(X + (size_t)(row0 + r) * 256 + c4 * 4)
                                   : make_float4(0.f, 0.f, 0.f, 0.f);
        Xs[r * XS_LD + c4 * 4 + 0] = __float2half_rn(v.x);
        Xs[r * XS_LD + c4 * 4 + 1] = __float2half_rn(v.y);
        Xs[r * XS_LD + c4 * 4 + 2] = __float2half_rn(v.z);
        Xs[r * XS_LD + c4 * 4 + 3] = __float2half_rn(v.w);
    }
    __syncthreads();

    for (int nc = 0; nc < 4; ++nc) {
        wmma::fragment<wmma::accumulator, 16, 16, 16, float> acc[2][4];
        #pragma unroll
        for (int i = 0; i < 2; ++i)
            #pragma unroll
            for (int j = 0; j < 4; ++j) wmma::fill_fragment(acc[i][j], 0.f);

        for (int kt = 0; kt < 4; ++kt) {
            #pragma unroll
            for (int p = 0; p < 4; ++p) {              // W1t tile [128n][64k]
                int idx = t + p * 256;
                int r = idx >> 3, c8 = idx & 7;
                *(uint4*)&Ws[r * WT_LD + c8 * 8] =
                    *(const uint4*)(g_W1t + (size_t)(nc * 128 + r) * 256 + kt * 64 + c8 * 8);
            }
            __syncthreads();
            #pragma unroll
            for (int ks = 0; ks < 4; ++ks) {
                wmma::fragment<wmma::matrix_a, 16, 16, 16, __half, wmma::row_major> a[2];
                wmma::fragment<wmma::matrix_b, 16, 16, 16, __half, wmma::col_major> b[4];
                #pragma unroll
                for (int i = 0; i < 2; ++i)
                    wmma::load_matrix_sync(a[i], Xs + (wm * 32 + i * 16) * XS_LD + kt * 64 + ks * 16, XS_LD);
                #pragma unroll
                for (int j = 0; j < 4; ++j)
                    wmma::load_matrix_sync(b[j], Ws + (wn * 64 + j * 16) * WT_LD + ks * 16, WT_LD);
                #pragma unroll
                for (int i = 0; i < 2; ++i)
                    #pragma unroll
                    for (int j = 0; j < 4; ++j)
                        wmma::mma_sync(acc[i][j], a[i], b[j], acc[i][j]);
            }
            __syncthreads();
        }
        // ---- epilogue: acc -> fbuf -> +b1, relu, fp16 -> g_H1 ----
        #pragma unroll
        for (int i = 0; i < 2; ++i)
            #pragma unroll
            for (int j = 0; j < 4; ++j)
                wmma::store_matrix_sync(fbuf + (wm * 32 + i * 16) * FB_LD + wn * 64 + j * 16,
                                        acc[i][j], FB_LD, wmma::mem_row_major);
        __syncthreads();
        #pragma unroll 4
        for (int p = 0; p < 64; ++p) {
            int idx = t + p * 256;
            int r = idx >> 7, c = idx & 127;
            if (row0 + r < Nn) {
                float v = fbuf[r * FB_LD + c] + b1[nc * 128 + c];
                v = v > 0.f ? v : 0.f;
                g_H1[(size_t)(row0 + r) * 512 + nc * 128 + c] = __float2half_rn(v);
            }
        }
        __syncthreads();
    }
}

// ============================================================================
// Kernel B: H2c = relu(H1@W2+b2); Y += H2c@W3c; silu; segment sum
// SMEM: Hs | W2s | Ps[2 tiles] | W3s  = 5 WT_TILE slots, then fbuf, gids.
// ============================================================================
__global__ void __launch_bounds__(256, 1)
gemm23_kernel(const int* __restrict__ gidx,
              const float* __restrict__ b2, const float* __restrict__ b3,
              float* __restrict__ out, int Nn)
{
    extern __shared__ char smem[];
    __half* Hs  = (__half*)smem;                 // [128][72]
    __half* W2s = Hs  + WT_TILE;
    __half* Ps  = W2s + WT_TILE;                 // 2 k-subtiles [128][72]
    __half* W3s = Ps  + 2 * WT_TILE;
    float*  fbuf = (float*)(W3s + WT_TILE);      // starts at 5*WT_TILE
    int*    gids = (int*)(fbuf + 128 * FB_LD);

    const int t   = threadIdx.x;
    const int wid = t >> 5;
    const int wm  = wid & 3;
    const int wn  = wid >> 2;
    const int row0 = blockIdx.x * 128;

    if (t < 128) gids[t] = (row0 + t < Nn) ? gidx[row0 + t] : -1;

    wmma::fragment<wmma::accumulator, 16, 16, 16, float> Y[2][4];
    #pragma unroll
    for (int i = 0; i < 2; ++i)
        #pragma unroll
        for (int j = 0; j < 4; ++j) wmma::fill_fragment(Y[i][j], 0.f);

    for (int mc = 0; mc < 4; ++mc) {
        wmma::fragment<wmma::accumulator, 16, 16, 16, float> acc2[2][4];
        #pragma unroll
        for (int i = 0; i < 2; ++i)
            #pragma unroll
            for (int j = 0; j < 4; ++j) wmma::fill_fragment(acc2[i][j], 0.f);

        // ---- GEMM2 chunk: acc2 = H1 @ W2t[mc*128..+128][:], kt = 0..7 ----
        for (int kt = 0; kt < 8; ++kt) {
            #pragma unroll
            for (int p = 0; p < 4; ++p) {              // H1 + W2 tiles [128][64]
                int idx = t + p * 256;
                int r = idx >> 3, c8 = idx & 7;
                size_t hsrc = (size_t)(row0 + r) * 512 + kt * 64 + c8 * 8;
                size_t wsrc = (size_t)(mc * 128 + r) * 512 + kt * 64 + c8 * 8;
                *(uint4*)&Hs[r * WT_LD + c8 * 8]  = *(const uint4*)(g_H1 + hsrc);
                *(uint4*)&W2s[r * WT_LD + c8 * 8] = *(const uint4*)(g_W2t + wsrc);
            }
            __syncthreads();
            #pragma unroll
            for (int ks = 0; ks < 4; ++ks) {
                wmma::fragment<wmma::matrix_a, 16, 16, 16, __half, wmma::row_major> a[2];
                wmma::fragment<wmma::matrix_b, 16, 16, 16, __half, wmma::col_major> b[4];
                #pragma unroll
                for (int i = 0; i < 2; ++i)
                    wmma::load_matrix_sync(a[i], Hs + (wm * 32 + i * 16) * WT_LD + ks * 16, WT_LD);
                #pragma unroll
                for (int j = 0; j < 4; ++j)
                    wmma::load_matrix_sync(b[j], W2s + (wn * 64 + j * 16) * WT_LD + ks * 16, WT_LD);
                #pragma unroll
                for (int i = 0; i < 2; ++i)
                    #pragma unroll
                    for (int j = 0; j < 4; ++j)
                        wmma::mma_sync(acc2[i][j], a[i], b[j], acc2[i][j]);
            }
            __syncthreads();
        }

        // ---- chunk epilogue: acc2 -> fbuf -> +b2, relu, fp16 -> Ps ----
        #pragma unroll
        for (int i = 0; i < 2; ++i)
            #pragma unroll
            for (int j = 0; j < 4; ++j)
                wmma::store_matrix_sync(fbuf + (wm * 32 + i * 16) * FB_LD + wn * 64 + j * 16,
                                        acc2[i][j], FB_LD, wmma::mem_row_major);
        __syncthreads();
        #pragma unroll 4
        for (int p = 0; p < 64; ++p) {
            int idx = t + p * 256;
            int r = idx >> 7, c = idx & 127;
            float v = fbuf[r * FB_LD + c] + b2[mc * 128 + c];
            v = v > 0.f ? v : 0.f;
            int sub = c >> 6, cc = c & 63;
            Ps[sub * WT_TILE + r * WT_LD + cc] = __float2half_rn(v);
        }
        __syncthreads();

        // ---- GEMM3 partial: Y += Ps @ W3t[:, mc*128..+128] ----
        for (int kt3 = 0; kt3 < 2; ++kt3) {
            #pragma unroll
            for (int p = 0; p < 4; ++p) {              // W3t tile [128n][64k]
                int idx = t + p * 256;
                int r = idx >> 3, c8 = idx & 7;
                *(uint4*)&W3s[r * WT_LD + c8 * 8] =
                    *(const uint4*)(g_W3t + (size_t)r * 512 + mc * 128 + kt3 * 64 + c8 * 8);
            }
            __syncthreads();
            #pragma unroll
            for (int ks = 0; ks < 4; ++ks) {
                wmma::fragment<wmma::matrix_a, 16, 16, 16, __half, wmma::row_major> a[2];
                wmma::fragment<wmma::matrix_b, 16, 16, 16, __half, wmma::col_major> b[4];
                #pragma unroll
                for (int i = 0; i < 2; ++i)
                    wmma::load_matrix_sync(a[i], Ps + kt3 * WT_TILE + (wm * 32 + i * 16) * WT_LD + ks * 16, WT_LD);
                #pragma unroll
                for (int j = 0; j < 4; ++j)
                    wmma::load_matrix_sync(b[j], W3s + (wn * 64 + j * 16) * WT_LD + ks * 16, WT_LD);
                #pragma unroll
                for (int i = 0; i < 2; ++i)
                    #pragma unroll
                    for (int j = 0; j < 4; ++j)
                        wmma::mma_sync(Y[i][j], a[i], b[j], Y[i][j]);
            }
            __syncthreads();
        }
    }

    // ---- final: Y -> fbuf, +b3, silu, sorted segment reduce, atomics ----
    #pragma unroll
    for (int i = 0; i < 2; ++i)
        #pragma unroll
        for (int j = 0; j < 4; ++j)
            wmma::store_matrix_sync(fbuf + (wm * 32 + i * 16) * FB_LD + wn * 64 + j * 16,
                                    Y[i][j], FB_LD, wmma::mem_row_major);
    __syncthreads();
    #pragma unroll 4
    for (int p = 0; p < 64; ++p) {
        int idx = t + p * 256;
        int r = idx >> 7, c = idx & 127;
        float y = fbuf[r * FB_LD + c] + b3[c];
        fbuf[r * FB_LD + c] = y / (1.f + expf(-y));
    }
    __syncthreads();

    if (t < 128) {
        int cur = gids[0];
        float s = 0.f;
        #pragma unroll 1
        for (int r = 0; r < 128; ++r) {
            int gi = gids[r];
            if (gi != cur) {
                if (cur >= 0) atomicAdd(&out[(size_t)cur * 128 + t], s);
                cur = gi; s = 0.f;
            }
            if (gi >= 0) s += fbuf[r * FB_LD + t];
        }
        if (cur >= 0) atomicAdd(&out[(size_t)cur * 128 + t], s);
    }
}

// ============================================================================
extern "C" void kernel_launch(void* const* d_in, const int* in_sizes, int n_in,
                              void* d_out, int out_size)
{
    const float* X    = (const float*)d_in[0];
    const int*   gidx = (const int*)d_in[1];     // int32 (JAX x64 disabled)
    const float* W1   = (const float*)d_in[2];
    const float* b1   = (const float*)d_in[3];
    const float* W2   = (const float*)d_in[4];
    const float* b2   = (const float*)d_in[5];
    const float* W3   = (const float*)d_in[6];
    const float* b3   = (const float*)d_in[7];
    float* out = (float*)d_out;

    const int Nn = in_sizes[0] / 256;
    const int blocks = (Nn + 127) / 128;

    zero_out_kernel<<<(out_size + 255) / 256, 256>>>(out, out_size);
    setup_weights<<<(512 * 256 + 512 * 512 + 128 * 512 + 255) / 256, 256>>>(W1, W2, W3);

    const int smemA = 128 * XS_LD * 2 + WT_TILE * 2 + 128 * FB_LD * 4;   // 153,600
    const int smemB = 5 * WT_TILE * 2 + 128 * FB_LD * 4 + 512;           // 160,256
    cudaFuncSetAttribute(gemm1_kernel,  cudaFuncAttributeMaxDynamicSharedMemorySize, smemA);
    cudaFuncSetAttribute(gemm23_kernel, cudaFuncAttributeMaxDynamicSharedMemorySize, smemB);

    gemm1_kernel<<<blocks, 256, smemA>>>(X, b1, Nn);
    gemm23_kernel<<<blocks, 256, smemB>>>(gidx, b2, b3, out, Nn);
}

// round 11
// speedup vs baseline: 3.5887x; 1.1473x over previous
#include <cuda_runtime.h>
#include <cuda_fp16.h>
#include <mma.h>
#include <math.h>
#include <cstdint>

using namespace nvcuda;

// ============================================================================
// Pure fp16 WMMA fused MLP + segment sum. 512 threads (4x4 warp grid, 32x32
// output per warp), cp.async double-buffered mainloops.
//   kernA: H1 = relu(X@W1+b1) -> g_H1 (fp16)
//   kernB: per 128-col chunk: H2c = relu(H1@W2+b2) -> smem fp16,
//          Y += H2c @ W3c, then g = silu(Y+b3), sorted segment-sum -> out.
// ============================================================================

#define NODES_PAD (3907 * 128)
#define XS_LD  264            // 256 + 8 pad (fp16 elems)
#define WT_LD  72             // 64 + 8 pad
#define WT_TILE (128 * WT_LD) // elems per [128x64] tile (18,432 B)
#define FB_LD  132            // fbuf fp32 ld

__device__ __align__(16) __half g_W1t[512 * 256];
__device__ __align__(16) __half g_W2t[512 * 512];
__device__ __align__(16) __half g_W3t[128 * 512];
__device__ __align__(16) __half g_H1[(size_t)NODES_PAD * 512];

__device__ __forceinline__ void cpa16(uint32_t dst, const void* src) {
    asm volatile("cp.async.cg.shared.global [%0], [%1], 16;" :: "r"(dst), "l"(src));
}
#define CPA_COMMIT() asm volatile("cp.async.commit_group;" ::: "memory")
#define CPA_WAIT0()  asm volatile("cp.async.wait_group 0;" ::: "memory")
#define CPA_WAIT1()  asm volatile("cp.async.wait_group 1;" ::: "memory")

// ---------------- setup: transpose weights to fp16 ----------------
__global__ void setup_weights(const float* __restrict__ W1, const float* __restrict__ W2,
                              const float* __restrict__ W3)
{
    int i = blockIdx.x * blockDim.x + threadIdx.x;
    if (i < 512 * 256) {
        int n = i >> 8, k = i & 255;
        g_W1t[n * 256 + k] = __float2half_rn(W1[k * 512 + n]);
        return;
    }
    i -= 512 * 256;
    if (i < 512 * 512) {
        int n = i >> 9, k = i & 511;
        g_W2t[n * 512 + k] = __float2half_rn(W2[k * 512 + n]);
        return;
    }
    i -= 512 * 512;
    if (i < 128 * 512) {
        int n = i >> 9, k = i & 511;
        g_W3t[n * 512 + k] = __float2half_rn(W3[k * 128 + n]);
    }
}

__global__ void zero_out_kernel(float* out, int n)
{
    int i = blockIdx.x * blockDim.x + threadIdx.x;
    if (i < n) out[i] = 0.f;
}

// ============================================================================
// Kernel A: H1 = relu(X @ W1 + b1).  512 threads.
// SMEM: Xs [128][264] resident | Ws 2 bufs x [128][72] | fbuf [128][132] f32
// ============================================================================
__global__ void __launch_bounds__(512, 1)
gemm1_kernel(const float* __restrict__ X, const float* __restrict__ b1, int Nn)
{
    extern __shared__ char smem[];
    __half* Xs = (__half*)smem;                       // 67,584 B
    __half* Ws = Xs + 128 * XS_LD;                    // 2 x 18,432 B
    float*  fbuf = (float*)(Ws + 2 * WT_TILE);        // 67,584 B
    const uint32_t wsu = (uint32_t)__cvta_generic_to_shared(Ws);

    const int t   = threadIdx.x;
    const int wid = t >> 5;
    const int wm  = wid & 3;          // 4 warps over M (32 rows)
    const int wn  = wid >> 2;         // 4 warps over N (32 cols)
    const int row0 = blockIdx.x * 128;

    // ---- load X (128 x 256 fp32) -> fp16 ----
    #pragma unroll 4
    for (int p = 0; p < 16; ++p) {
        int idx = t + p * 512;
        int r = idx >> 6, c4 = idx & 63;
        float4 v = (row0 + r < Nn) ? *(const float4*)(X + (size_t)(row0 + r) * 256 + c4 * 4)
                                   : make_float4(0.f, 0.f, 0.f, 0.f);
        Xs[r * XS_LD + c4 * 4 + 0] = __float2half_rn(v.x);
        Xs[r * XS_LD + c4 * 4 + 1] = __float2half_rn(v.y);
        Xs[r * XS_LD + c4 * 4 + 2] = __float2half_rn(v.z);
        Xs[r * XS_LD + c4 * 4 + 3] = __float2half_rn(v.w);
    }
    __syncthreads();

    auto prefW = [&](int nc, int kt, int b) {
        const uint32_t base = wsu + (uint32_t)b * WT_TILE * 2;
        #pragma unroll
        for (int p = 0; p < 2; ++p) {
            int idx = t + p * 512;
            int r = idx >> 3, c8 = idx & 7;
            cpa16(base + (uint32_t)(r * WT_LD + c8 * 8) * 2,
                  g_W1t + (size_t)(nc * 128 + r) * 256 + kt * 64 + c8 * 8);
        }
    };

    for (int nc = 0; nc < 4; ++nc) {
        wmma::fragment<wmma::accumulator, 16, 16, 16, float> acc[2][2];
        #pragma unroll
        for (int i = 0; i < 2; ++i)
            #pragma unroll
            for (int j = 0; j < 2; ++j) wmma::fill_fragment(acc[i][j], 0.f);

        prefW(nc, 0, 0); CPA_COMMIT();
        for (int kt = 0; kt < 4; ++kt) {
            if (kt < 3) { prefW(nc, kt + 1, (kt + 1) & 1); CPA_COMMIT(); CPA_WAIT1(); }
            else        { CPA_WAIT0(); }
            __syncthreads();
            const __half* Wb = Ws + (kt & 1) * WT_TILE;
            #pragma unroll
            for (int ks = 0; ks < 4; ++ks) {
                wmma::fragment<wmma::matrix_a, 16, 16, 16, __half, wmma::row_major> a[2];
                wmma::fragment<wmma::matrix_b, 16, 16, 16, __half, wmma::col_major> b[2];
                #pragma unroll
                for (int i = 0; i < 2; ++i)
                    wmma::load_matrix_sync(a[i], Xs + (wm * 32 + i * 16) * XS_LD + kt * 64 + ks * 16, XS_LD);
                #pragma unroll
                for (int j = 0; j < 2; ++j)
                    wmma::load_matrix_sync(b[j], Wb + (wn * 32 + j * 16) * WT_LD + ks * 16, WT_LD);
                #pragma unroll
                for (int i = 0; i < 2; ++i)
                    #pragma unroll
                    for (int j = 0; j < 2; ++j)
                        wmma::mma_sync(acc[i][j], a[i], b[j], acc[i][j]);
            }
            __syncthreads();
        }
        // ---- epilogue: acc -> fbuf -> +b1, relu, fp16 -> g_H1 ----
        #pragma unroll
        for (int i = 0; i < 2; ++i)
            #pragma unroll
            for (int j = 0; j < 2; ++j)
                wmma::store_matrix_sync(fbuf + (wm * 32 + i * 16) * FB_LD + wn * 32 + j * 16,
                                        acc[i][j], FB_LD, wmma::mem_row_major);
        __syncthreads();
        #pragma unroll 4
        for (int p = 0; p < 32; ++p) {
            int idx = t + p * 512;
            int r = idx >> 7, c = idx & 127;
            if (row0 + r < Nn) {
                float v = fbuf[r * FB_LD + c] + b1[nc * 128 + c];
                v = v > 0.f ? v : 0.f;
                g_H1[(size_t)(row0 + r) * 512 + nc * 128 + c] = __float2half_rn(v);
            }
        }
        __syncthreads();
    }
}

// ============================================================================
// Kernel B: H2c = relu(H1@W2+b2); Y += H2c@W3c; silu; segment sum. 512 thr.
// SMEM: stage bufs 2 x (Hs,W2s) = 4 tiles | Ps 2 tiles | W3s 1 tile |
//       fbuf [128][132] f32 | gids.   (7 x WT_TILE + fbuf + gids = 197,120 B)
// ============================================================================
__global__ void __launch_bounds__(512, 1)
gemm23_kernel(const int* __restrict__ gidx,
              const float* __restrict__ b2, const float* __restrict__ b3,
              float* __restrict__ out, int Nn)
{
    extern __shared__ char smem[];
    __half* SG  = (__half*)smem;                 // 2 stages x (Hs, W2s)
    __half* Ps  = SG + 4 * WT_TILE;              // 2 k-subtiles
    __half* W3s = Ps + 2 * WT_TILE;
    float*  fbuf = (float*)(W3s + WT_TILE);
    int*    gids = (int*)(fbuf + 128 * FB_LD);
    const uint32_t sgu = (uint32_t)__cvta_generic_to_shared(SG);

    const int t   = threadIdx.x;
    const int wid = t >> 5;
    const int wm  = wid & 3;
    const int wn  = wid >> 2;
    const int row0 = blockIdx.x * 128;

    if (t < 128) gids[t] = (row0 + t < Nn) ? gidx[row0 + t] : -1;

    auto prefG2 = [&](int mc, int kt, int b) {
        const uint32_t base = sgu + (uint32_t)b * 2 * WT_TILE * 2;
        #pragma unroll
        for (int p = 0; p < 2; ++p) {
            int idx = t + p * 512;
            int r = idx >> 3, c8 = idx & 7;
            uint32_t off = (uint32_t)(r * WT_LD + c8 * 8) * 2;
            cpa16(base + off,               g_H1  + (size_t)(row0 + r) * 512 + kt * 64 + c8 * 8);
            cpa16(base + WT_TILE * 2 + off, g_W2t + (size_t)(mc * 128 + r) * 512 + kt * 64 + c8 * 8);
        }
    };

    wmma::fragment<wmma::accumulator, 16, 16, 16, float> Y[2][2];
    #pragma unroll
    for (int i = 0; i < 2; ++i)
        #pragma unroll
        for (int j = 0; j < 2; ++j) wmma::fill_fragment(Y[i][j], 0.f);

    for (int mc = 0; mc < 4; ++mc) {
        wmma::fragment<wmma::accumulator, 16, 16, 16, float> acc2[2][2];
        #pragma unroll
        for (int i = 0; i < 2; ++i)
            #pragma unroll
            for (int j = 0; j < 2; ++j) wmma::fill_fragment(acc2[i][j], 0.f);

        // ---- GEMM2 chunk, cp.async double-buffered, kt = 0..7 ----
        prefG2(mc, 0, 0); CPA_COMMIT();
        for (int kt = 0; kt < 8; ++kt) {
            if (kt < 7) { prefG2(mc, kt + 1, (kt + 1) & 1); CPA_COMMIT(); CPA_WAIT1(); }
            else        { CPA_WAIT0(); }
            __syncthreads();
            const __half* Hs  = SG + (kt & 1) * 2 * WT_TILE;
            const __half* W2s = Hs + WT_TILE;
            #pragma unroll
            for (int ks = 0; ks < 4; ++ks) {
                wmma::fragment<wmma::matrix_a, 16, 16, 16, __half, wmma::row_major> a[2];
                wmma::fragment<wmma::matrix_b, 16, 16, 16, __half, wmma::col_major> b[2];
                #pragma unroll
                for (int i = 0; i < 2; ++i)
                    wmma::load_matrix_sync(a[i], Hs + (wm * 32 + i * 16) * WT_LD + ks * 16, WT_LD);
                #pragma unroll
                for (int j = 0; j < 2; ++j)
                    wmma::load_matrix_sync(b[j], W2s + (wn * 32 + j * 16) * WT_LD + ks * 16, WT_LD);
                #pragma unroll
                for (int i = 0; i < 2; ++i)
                    #pragma unroll
                    for (int j = 0; j < 2; ++j)
                        wmma::mma_sync(acc2[i][j], a[i], b[j], acc2[i][j]);
            }
            __syncthreads();
        }

        // ---- chunk epilogue: acc2 -> fbuf -> +b2, relu, fp16 -> Ps ----
        #pragma unroll
        for (int i = 0; i < 2; ++i)
            #pragma unroll
            for (int j = 0; j < 2; ++j)
                wmma::store_matrix_sync(fbuf + (wm * 32 + i * 16) * FB_LD + wn * 32 + j * 16,
                                        acc2[i][j], FB_LD, wmma::mem_row_major);
        __syncthreads();
        #pragma unroll 4
        for (int p = 0; p < 32; ++p) {
            int idx = t + p * 512;
            int r = idx >> 7, c = idx & 127;
            float v = fbuf[r * FB_LD + c] + b2[mc * 128 + c];
            v = v > 0.f ? v : 0.f;
            int sub = c >> 6, cc = c & 63;
            Ps[sub * WT_TILE + r * WT_LD + cc] = __float2half_rn(v);
        }
        __syncthreads();

        // ---- GEMM3 partial: Y += Ps @ W3t[:, mc*128..+128] ----
        for (int kt3 = 0; kt3 < 2; ++kt3) {
            #pragma unroll
            for (int p = 0; p < 2; ++p) {              // W3t tile [128n][64k]
                int idx = t + p * 512;
                int r = idx >> 3, c8 = idx & 7;
                *(uint4*)&W3s[r * WT_LD + c8 * 8] =
                    *(const uint4*)(g_W3t + (size_t)r * 512 + mc * 128 + kt3 * 64 + c8 * 8);
            }
            __syncthreads();
            #pragma unroll
            for (int ks = 0; ks < 4; ++ks) {
                wmma::fragment<wmma::matrix_a, 16, 16, 16, __half, wmma::row_major> a[2];
                wmma::fragment<wmma::matrix_b, 16, 16, 16, __half, wmma::col_major> b[2];
                #pragma unroll
                for (int i = 0; i < 2; ++i)
                    wmma::load_matrix_sync(a[i], Ps + kt3 * WT_TILE + (wm * 32 + i * 16) * WT_LD + ks * 16, WT_LD);
                #pragma unroll
                for (int j = 0; j < 2; ++j)
                    wmma::load_matrix_sync(b[j], W3s + (wn * 32 + j * 16) * WT_LD + ks * 16, WT_LD);
                #pragma unroll
                for (int i = 0; i < 2; ++i)
                    #pragma unroll
                    for (int j = 0; j < 2; ++j)
                        wmma::mma_sync(Y[i][j], a[i], b[j], Y[i][j]);
            }
            __syncthreads();
        }
    }

    // ---- final: Y -> fbuf, +b3, silu, sorted segment reduce, atomics ----
    #pragma unroll
    for (int i = 0; i < 2; ++i)
        #pragma unroll
        for (int j = 0; j < 2; ++j)
            wmma::store_matrix_sync(fbuf + (wm * 32 + i * 16) * FB_LD + wn * 32 + j * 16,
                                    Y[i][j], FB_LD, wmma::mem_row_major);
    __syncthreads();
    #pragma unroll 4
    for (int p = 0; p < 32; ++p) {
        int idx = t + p * 512;
        int r = idx >> 7, c = idx & 127;
        float y = fbuf[r * FB_LD + c] + b3[c];
        fbuf[r * FB_LD + c] = y / (1.f + expf(-y));
    }
    __syncthreads();

    if (t < 128) {
        int cur = gids[0];
        float s = 0.f;
        #pragma unroll 1
        for (int r = 0; r < 128; ++r) {
            int gi = gids[r];
            if (gi != cur) {
                if (cur >= 0) atomicAdd(&out[(size_t)cur * 128 + t], s);
                cur = gi; s = 0.f;
            }
            if (gi >= 0) s += fbuf[r * FB_LD + t];
        }
        if (cur >= 0) atomicAdd(&out[(size_t)cur * 128 + t], s);
    }
}

// ============================================================================
extern "C" void kernel_launch(void* const* d_in, const int* in_sizes, int n_in,
                              void* d_out, int out_size)
{
    const float* X    = (const float*)d_in[0];
    const int*   gidx = (const int*)d_in[1];     // int32 (JAX x64 disabled)
    const float* W1   = (const float*)d_in[2];
    const float* b1   = (const float*)d_in[3];
    const float* W2   = (const float*)d_in[4];
    const float* b2   = (const float*)d_in[5];
    const float* W3   = (const float*)d_in[6];
    const float* b3   = (const float*)d_in[7];
    float* out = (float*)d_out;

    const int Nn = in_sizes[0] / 256;
    const int blocks = (Nn + 127) / 128;

    zero_out_kernel<<<(out_size + 255) / 256, 256>>>(out, out_size);
    setup_weights<<<(512 * 256 + 512 * 512 + 128 * 512 + 255) / 256, 256>>>(W1, W2, W3);

    const int smemA = 128 * XS_LD * 2 + 2 * WT_TILE * 2 + 128 * FB_LD * 4;   // 172,032
    const int smemB = 7 * WT_TILE * 2 + 128 * FB_LD * 4 + 512;               // 197,120
    cudaFuncSetAttribute(gemm1_kernel,  cudaFuncAttributeMaxDynamicSharedMemorySize, smemA);
    cudaFuncSetAttribute(gemm23_kernel, cudaFuncAttributeMaxDynamicSharedMemorySize, smemB);

    gemm1_kernel<<<blocks, 512, smemA>>>(X, b1, Nn);
    gemm23_kernel<<<blocks, 512, smemB>>>(gidx, b2, b3, out, Nn);
}

// round 12
// speedup vs baseline: 3.8913x; 1.0843x over previous
#include <cuda_runtime.h>
#include <cuda_fp16.h>
#include <mma.h>
#include <math.h>
#include <cstdint>

using namespace nvcuda;

// ============================================================================
// Pure fp16 WMMA fused MLP + segment sum. 512 threads, warp tile 32x64
// (frag-load:MMA ratio 0.75), N-chunks of 256, cp.async 2-stage pipeline.
//   kernA: H1 = relu(X@W1+b1) -> g_H1 (fp16)
//   kernB: per 256-col chunk: H2c = relu(H1@W2+b2) -> smem fp16 (Ps),
//          Y += H2c @ W3c, then g = silu(Y+b3), sorted segment-sum -> out.
// fbuf aliases the (idle) cp.async stage buffers during epilogues.
// ============================================================================

#define NODES_PAD (3907 * 128)
#define XS_LD  264             // 256 + 8 pad (fp16 elems)
#define WT_LD  72              // 64 + 8 pad
#define T128   (128 * WT_LD)   // [128x64] tile elems (18,432 B)
#define T256   (256 * WT_LD)   // [256x64] tile elems (36,864 B)
#define STG    (T128 + T256)   // kernel-B stage stride (Hs + W2s)
#define FB_LD  132             // fbuf fp32 ld

__device__ __align__(16) __half g_W1t[512 * 256];
__device__ __align__(16) __half g_W2t[512 * 512];
__device__ __align__(16) __half g_W3t[128 * 512];
__device__ __align__(16) __half g_H1[(size_t)NODES_PAD * 512];

__device__ __forceinline__ void cpa16(uint32_t dst, const void* src) {
    asm volatile("cp.async.cg.shared.global [%0], [%1], 16;" :: "r"(dst), "l"(src));
}
#define CPA_COMMIT() asm volatile("cp.async.commit_group;" ::: "memory")
#define CPA_WAIT0()  asm volatile("cp.async.wait_group 0;" ::: "memory")
#define CPA_WAIT1()  asm volatile("cp.async.wait_group 1;" ::: "memory")

// ---------------- setup: transpose weights to fp16 ----------------
__global__ void setup_weights(const float* __restrict__ W1, const float* __restrict__ W2,
                              const float* __restrict__ W3)
{
    int i = blockIdx.x * blockDim.x + threadIdx.x;
    if (i < 512 * 256) {
        int n = i >> 8, k = i & 255;
        g_W1t[n * 256 + k] = __float2half_rn(W1[k * 512 + n]);
        return;
    }
    i -= 512 * 256;
    if (i < 512 * 512) {
        int n = i >> 9, k = i & 511;
        g_W2t[n * 512 + k] = __float2half_rn(W2[k * 512 + n]);
        return;
    }
    i -= 512 * 512;
    if (i < 128 * 512) {
        int n = i >> 9, k = i & 511;
        g_W3t[n * 512 + k] = __float2half_rn(W3[k * 128 + n]);
    }
}

__global__ void zero_out_kernel(float* out, int n)
{
    int i = blockIdx.x * blockDim.x + threadIdx.x;
    if (i < n) out[i] = 0.f;
}

// ============================================================================
// Kernel A: H1 = relu(X @ W1 + b1).  512 threads, 2 N-chunks of 256.
// SMEM: Xs [128][264] resident | SW 2 stages x [256][72]  (fbuf aliases SW)
// ============================================================================
__global__ void __launch_bounds__(512, 1)
gemm1_kernel(const float* __restrict__ X, const float* __restrict__ b1, int Nn)
{
    extern __shared__ char smem[];
    __half* Xs = (__half*)smem;                       // 67,584 B
    __half* SW = Xs + 128 * XS_LD;                    // 2 x 36,864 B
    float*  fbuf = (float*)SW;                        // alias (stages idle)
    const uint32_t swu = (uint32_t)__cvta_generic_to_shared(SW);

    const int t   = threadIdx.x;
    const int wid = t >> 5;
    const int wm  = wid & 3;          // 4 warps over M (32 rows each)
    const int wn  = wid >> 2;         // 4 warps over N (64 cols each)
    const int row0 = blockIdx.x * 128;

    // ---- load X (128 x 256 fp32) -> fp16 ----
    #pragma unroll 4
    for (int p = 0; p < 16; ++p) {
        int idx = t + p * 512;
        int r = idx >> 6, c4 = idx & 63;
        float4 v = (row0 + r < Nn) ? *(const float4*)(X + (size_t)(row0 + r) * 256 + c4 * 4)
                                   : make_float4(0.f, 0.f, 0.f, 0.f);
        Xs[r * XS_LD + c4 * 4 + 0] = __float2half_rn(v.x);
        Xs[r * XS_LD + c4 * 4 + 1] = __float2half_rn(v.y);
        Xs[r * XS_LD + c4 * 4 + 2] = __float2half_rn(v.z);
        Xs[r * XS_LD + c4 * 4 + 3] = __float2half_rn(v.w);
    }
    __syncthreads();

    auto prefW = [&](int nc, int kt, int b) {         // W1t tile [256n][64k]
        const uint32_t base = swu + (uint32_t)b * T256 * 2;
        #pragma unroll
        for (int p = 0; p < 4; ++p) {
            int idx = t + p * 512;
            int r = idx >> 3, c8 = idx & 7;
            cpa16(base + (uint32_t)(r * WT_LD + c8 * 8) * 2,
                  g_W1t + (size_t)(nc * 256 + r) * 256 + kt * 64 + c8 * 8);
        }
    };

    for (int nc = 0; nc < 2; ++nc) {
        wmma::fragment<wmma::accumulator, 16, 16, 16, float> acc[2][4];
        #pragma unroll
        for (int i = 0; i < 2; ++i)
            #pragma unroll
            for (int j = 0; j < 4; ++j) wmma::fill_fragment(acc[i][j], 0.f);

        prefW(nc, 0, 0); CPA_COMMIT();
        for (int kt = 0; kt < 4; ++kt) {
            if (kt < 3) { prefW(nc, kt + 1, (kt + 1) & 1); CPA_COMMIT(); CPA_WAIT1(); }
            else        { CPA_WAIT0(); }
            __syncthreads();
            const __half* Wb = SW + (kt & 1) * T256;
            #pragma unroll
            for (int ks = 0; ks < 4; ++ks) {
                wmma::fragment<wmma::matrix_a, 16, 16, 16, __half, wmma::row_major> a[2];
                wmma::fragment<wmma::matrix_b, 16, 16, 16, __half, wmma::col_major> b[4];
                #pragma unroll
                for (int i = 0; i < 2; ++i)
                    wmma::load_matrix_sync(a[i], Xs + (wm * 32 + i * 16) * XS_LD + kt * 64 + ks * 16, XS_LD);
                #pragma unroll
                for (int j = 0; j < 4; ++j)
                    wmma::load_matrix_sync(b[j], Wb + (wn * 64 + j * 16) * WT_LD + ks * 16, WT_LD);
                #pragma unroll
                for (int i = 0; i < 2; ++i)
                    #pragma unroll
                    for (int j = 0; j < 4; ++j)
                        wmma::mma_sync(acc[i][j], a[i], b[j], acc[i][j]);
            }
            __syncthreads();
        }
        // ---- epilogue: two 128-col passes through fbuf (aliases SW) ----
        #pragma unroll 1
        for (int h = 0; h < 2; ++h) {
            if ((wn >> 1) == h) {
                #pragma unroll
                for (int i = 0; i < 2; ++i)
                    #pragma unroll
                    for (int j = 0; j < 4; ++j)
                        wmma::store_matrix_sync(fbuf + (wm * 32 + i * 16) * FB_LD + (wn & 1) * 64 + j * 16,
                                                acc[i][j], FB_LD, wmma::mem_row_major);
            }
            __syncthreads();
            int col0 = nc * 256 + h * 128;
            #pragma unroll 4
            for (int p = 0; p < 32; ++p) {
                int idx = t + p * 512;
                int r = idx >> 7, c = idx & 127;
                if (row0 + r < Nn) {
                    float v = fbuf[r * FB_LD + c] + b1[col0 + c];
                    v = v > 0.f ? v : 0.f;
                    g_H1[(size_t)(row0 + r) * 512 + col0 + c] = __float2half_rn(v);
                }
            }
            __syncthreads();
        }
    }
}

// ============================================================================
// Kernel B: 2 N-chunks of 256. 512 threads.
// SMEM: SG 2 stages x (Hs [128][72] + W2s [256][72]) | Ps 4 x [128][72] |
//       W3s [128][72] | gids.  fbuf [128][132] f32 aliases SG.
// ============================================================================
__global__ void __launch_bounds__(512, 1)
gemm23_kernel(const int* __restrict__ gidx,
              const float* __restrict__ b2, const float* __restrict__ b3,
              float* __restrict__ out, int Nn)
{
    extern __shared__ char smem[];
    __half* SG  = (__half*)smem;                 // 2 x STG
    __half* Ps  = SG + 2 * STG;                  // 4 k-subtiles [128][72]
    __half* W3s = Ps + 4 * T128;
    int*    gids = (int*)(W3s + T128);
    float*  fbuf = (float*)SG;                   // alias (stages idle)
    const uint32_t sgu = (uint32_t)__cvta_generic_to_shared(SG);

    const int t   = threadIdx.x;
    const int wid = t >> 5;
    const int wm  = wid & 3;
    const int wn  = wid >> 2;
    const int row0 = blockIdx.x * 128;

    if (t < 128) gids[t] = (row0 + t < Nn) ? gidx[row0 + t] : -1;

    auto prefG2 = [&](int mc, int kt, int b) {
        const uint32_t base = sgu + (uint32_t)b * STG * 2;
        #pragma unroll
        for (int p = 0; p < 2; ++p) {            // Hs [128][64]
            int idx = t + p * 512;
            int r = idx >> 3, c8 = idx & 7;
            cpa16(base + (uint32_t)(r * WT_LD + c8 * 8) * 2,
                  g_H1 + (size_t)(row0 + r) * 512 + kt * 64 + c8 * 8);
        }
        #pragma unroll
        for (int p = 0; p < 4; ++p) {            // W2s [256][64]
            int idx = t + p * 512;
            int r = idx >> 3, c8 = idx & 7;
            cpa16(base + (uint32_t)T128 * 2 + (uint32_t)(r * WT_LD + c8 * 8) * 2,
                  g_W2t + (size_t)(mc * 256 + r) * 512 + kt * 64 + c8 * 8);
        }
    };

    wmma::fragment<wmma::accumulator, 16, 16, 16, float> Y[2][2];
    #pragma unroll
    for (int i = 0; i < 2; ++i)
        #pragma unroll
        for (int j = 0; j < 2; ++j) wmma::fill_fragment(Y[i][j], 0.f);

    for (int mc = 0; mc < 2; ++mc) {
        wmma::fragment<wmma::accumulator, 16, 16, 16, float> acc2[2][4];
        #pragma unroll
        for (int i = 0; i < 2; ++i)
            #pragma unroll
            for (int j = 0; j < 4; ++j) wmma::fill_fragment(acc2[i][j], 0.f);

        // ---- GEMM2 chunk, cp.async 2-stage, kt = 0..7 ----
        prefG2(mc, 0, 0); CPA_COMMIT();
        for (int kt = 0; kt < 8; ++kt) {
            if (kt < 7) { prefG2(mc, kt + 1, (kt + 1) & 1); CPA_COMMIT(); CPA_WAIT1(); }
            else        { CPA_WAIT0(); }
            __syncthreads();
            const __half* Hs  = SG + (kt & 1) * STG;
            const __half* W2s = Hs + T128;
            #pragma unroll
            for (int ks = 0; ks < 4; ++ks) {
                wmma::fragment<wmma::matrix_a, 16, 16, 16, __half, wmma::row_major> a[2];
                wmma::fragment<wmma::matrix_b, 16, 16, 16, __half, wmma::col_major> b[4];
                #pragma unroll
                for (int i = 0; i < 2; ++i)
                    wmma::load_matrix_sync(a[i], Hs + (wm * 32 + i * 16) * WT_LD + ks * 16, WT_LD);
                #pragma unroll
                for (int j = 0; j < 4; ++j)
                    wmma::load_matrix_sync(b[j], W2s + (wn * 64 + j * 16) * WT_LD + ks * 16, WT_LD);
                #pragma unroll
                for (int i = 0; i < 2; ++i)
                    #pragma unroll
                    for (int j = 0; j < 4; ++j)
                        wmma::mma_sync(acc2[i][j], a[i], b[j], acc2[i][j]);
            }
            __syncthreads();
        }

        // ---- chunk epilogue: two 128-col passes, fbuf aliases SG ----
        #pragma unroll 1
        for (int h = 0; h < 2; ++h) {
            if ((wn >> 1) == h) {
                #pragma unroll
                for (int i = 0; i < 2; ++i)
                    #pragma unroll
                    for (int j = 0; j < 4; ++j)
                        wmma::store_matrix_sync(fbuf + (wm * 32 + i * 16) * FB_LD + (wn & 1) * 64 + j * 16,
                                                acc2[i][j], FB_LD, wmma::mem_row_major);
            }
            __syncthreads();
            #pragma unroll 4
            for (int p = 0; p < 32; ++p) {
                int idx = t + p * 512;
                int r = idx >> 7, c = idx & 127;
                float v = fbuf[r * FB_LD + c] + b2[mc * 256 + h * 128 + c];
                v = v > 0.f ? v : 0.f;
                int sub = h * 2 + (c >> 6);
                Ps[sub * T128 + r * WT_LD + (c & 63)] = __float2half_rn(v);
            }
            __syncthreads();
        }

        // ---- GEMM3 partial: Y += Ps (128x256) @ W3t[:, mc*256..+256] ----
        for (int kt3 = 0; kt3 < 4; ++kt3) {
            #pragma unroll
            for (int p = 0; p < 2; ++p) {        // W3t tile [128n][64k]
                int idx = t + p * 512;
                int r = idx >> 3, c8 = idx & 7;
                *(uint4*)&W3s[r * WT_LD + c8 * 8] =
                    *(const uint4*)(g_W3t + (size_t)r * 512 + mc * 256 + kt3 * 64 + c8 * 8);
            }
            __syncthreads();
            #pragma unroll
            for (int ks = 0; ks < 4; ++ks) {
                wmma::fragment<wmma::matrix_a, 16, 16, 16, __half, wmma::row_major> a[2];
                wmma::fragment<wmma::matrix_b, 16, 16, 16, __half, wmma::col_major> b[2];
                #pragma unroll
                for (int i = 0; i < 2; ++i)
                    wmma::load_matrix_sync(a[i], Ps + kt3 * T128 + (wm * 32 + i * 16) * WT_LD + ks * 16, WT_LD);
                #pragma unroll
                for (int j = 0; j < 2; ++j)
                    wmma::load_matrix_sync(b[j], W3s + (wn * 32 + j * 16) * WT_LD + ks * 16, WT_LD);
                #pragma unroll
                for (int i = 0; i < 2; ++i)
                    #pragma unroll
                    for (int j = 0; j < 2; ++j)
                        wmma::mma_sync(Y[i][j], a[i], b[j], Y[i][j]);
            }
            __syncthreads();
        }
    }

    // ---- final: Y -> fbuf, +b3, silu, sorted segment reduce, atomics ----
    #pragma unroll
    for (int i = 0; i < 2; ++i)
        #pragma unroll
        for (int j = 0; j < 2; ++j)
            wmma::store_matrix_sync(fbuf + (wm * 32 + i * 16) * FB_LD + wn * 32 + j * 16,
                                    Y[i][j], FB_LD, wmma::mem_row_major);
    __syncthreads();
    #pragma unroll 4
    for (int p = 0; p < 32; ++p) {
        int idx = t + p * 512;
        int r = idx >> 7, c = idx & 127;
        float y = fbuf[r * FB_LD + c] + b3[c];
        fbuf[r * FB_LD + c] = y / (1.f + expf(-y));
    }
    __syncthreads();

    if (t < 128) {
        int cur = gids[0];
        float s = 0.f;
        #pragma unroll 1
        for (int r = 0; r < 128; ++r) {
            int gi = gids[r];
            if (gi != cur) {
                if (cur >= 0) atomicAdd(&out[(size_t)cur * 128 + t], s);
                cur = gi; s = 0.f;
            }
            if (gi >= 0) s += fbuf[r * FB_LD + t];
        }
        if (cur >= 0) atomicAdd(&out[(size_t)cur * 128 + t], s);
    }
}

// ============================================================================
extern "C" void kernel_launch(void* const* d_in, const int* in_sizes, int n_in,
                              void* d_out, int out_size)
{
    const float* X    = (const float*)d_in[0];
    const int*   gidx = (const int*)d_in[1];     // int32 (JAX x64 disabled)
    const float* W1   = (const float*)d_in[2];
    const float* b1   = (const float*)d_in[3];
    const float* W2   = (const float*)d_in[4];
    const float* b2   = (const float*)d_in[5];
    const float* W3   = (const float*)d_in[6];
    const float* b3   = (const float*)d_in[7];
    float* out = (float*)d_out;

    const int Nn = in_sizes[0] / 256;
    const int blocks = (Nn + 127) / 128;

    zero_out_kernel<<<(out_size + 255) / 256, 256>>>(out, out_size);
    setup_weights<<<(512 * 256 + 512 * 512 + 128 * 512 + 255) / 256, 256>>>(W1, W2, W3);

    const int smemA = 128 * XS_LD * 2 + 2 * T256 * 2;                    // 141,312
    const int smemB = 2 * STG * 2 + 4 * T128 * 2 + T128 * 2 + 512;       // 203,264
    cudaFuncSetAttribute(gemm1_kernel,  cudaFuncAttributeMaxDynamicSharedMemorySize, smemA);
    cudaFuncSetAttribute(gemm23_kernel, cudaFuncAttributeMaxDynamicSharedMemorySize, smemB);

    gemm1_kernel<<<blocks, 512, smemA>>>(X, b1, Nn);
    gemm23_kernel<<<blocks, 512, smemB>>>(gidx, b2, b3, out, Nn);
}